// round 1
// baseline (speedup 1.0000x reference)
#include <cuda_runtime.h>
#include <cuda_bf16.h>
#include <cstdint>

#define N_NODES 100000
#define HID     128
#define N_EDGES 1600000

// Scratch (allocation-free rule: __device__ globals)
__device__ float g_SI[2u * N_NODES * HID];   // [0]=S, [1]=I  (102.4 MB)
__device__ float g_AI[(size_t)N_NODES * HID]; // 51.2 MB

// ---------------------------------------------------------------------------
// packed fp32x2 FMA (Blackwell FFMA2 — only reachable via PTX)
// ---------------------------------------------------------------------------
__device__ __forceinline__ void fma_f32x2(unsigned long long& d,
                                          unsigned long long a,
                                          unsigned long long b) {
    asm("fma.rn.f32x2 %0, %1, %2, %3;" : "=l"(d) : "l"(a), "l"(b), "l"(d));
}

// ---------------------------------------------------------------------------
// Kernel 0: zero AI accumulator
// ---------------------------------------------------------------------------
__global__ void __launch_bounds__(256) zero_ai_kernel() {
    size_t i = (size_t)blockIdx.x * 256 + threadIdx.x;   // N*H/4 = 3.2M float4
    ((float4*)g_AI)[i] = make_float4(0.f, 0.f, 0.f, 0.f);
}

// ---------------------------------------------------------------------------
// Kernel 1: S/I = sigmoid(x[s] @ W^T + b), s in {0,1}
// Block tile 128 rows x 128 cols, 256 threads, 8x8 per-thread regs, f32x2 on k.
// SMEM: Xs[128][128] + Ws[c][k] padded to 130 + Bs[128]  = 132608 B (dynamic)
// ---------------------------------------------------------------------------
#define WPAD 130
__global__ void __launch_bounds__(256, 1)
gemm_sigmoid_kernel(const float* __restrict__ x,
                    const float* __restrict__ W,
                    const float* __restrict__ b) {
    extern __shared__ float sm[];
    float* Xs = sm;                     // 128*128
    float* Ws = sm + 128 * 128;         // 128*WPAD, layout [c][k]
    float* Bs = Ws + 128 * WPAD;        // 128

    const int s    = blockIdx.y;
    const int row0 = blockIdx.x * 128;
    const int tid  = threadIdx.x;

    // Load W into SMEM as Ws[c*WPAD + k] (k contiguous for f32x2 pair loads)
    for (int idx = tid; idx < 128 * 128; idx += 256) {
        int c = idx >> 7, k = idx & 127;
        Ws[c * WPAD + k] = W[idx];
    }
    if (tid < 128) Bs[tid] = b[tid];

    // Load X tile (reads past N stay inside the x buffer since s<=1; outputs
    // for rows >= N are never written)
    const float4* xs4 = (const float4*)(x + ((size_t)s * N_NODES + row0) * HID);
    for (int idx = tid; idx < 128 * 32; idx += 256)
        ((float4*)Xs)[idx] = xs4[idx];
    __syncthreads();

    const int ty = tid >> 4;       // 0..15  -> 8 rows each
    const int tx = tid & 15;       // 0..15  -> cols tx + 16*j

    unsigned long long acc[8][8];
#pragma unroll
    for (int i = 0; i < 8; i++)
#pragma unroll
        for (int j = 0; j < 8; j++) acc[i][j] = 0ull;

#pragma unroll 4
    for (int k = 0; k < 128; k += 2) {
        unsigned long long xv[8], wv[8];
#pragma unroll
        for (int i = 0; i < 8; i++)
            xv[i] = *(const unsigned long long*)(Xs + (ty * 8 + i) * 128 + k);
#pragma unroll
        for (int j = 0; j < 8; j++)
            wv[j] = *(const unsigned long long*)(Ws + (tx + 16 * j) * WPAD + k);
#pragma unroll
        for (int j = 0; j < 8; j++)
#pragma unroll
            for (int i = 0; i < 8; i++)
                fma_f32x2(acc[i][j], xv[i], wv[j]);
    }

    float* outS = g_SI + ((size_t)s * N_NODES + row0) * HID;
#pragma unroll
    for (int i = 0; i < 8; i++) {
        int r = ty * 8 + i;
        if (row0 + r < N_NODES) {
#pragma unroll
            for (int j = 0; j < 8; j++) {
                int c = tx + 16 * j;
                unsigned long long a = acc[i][j];
                float lo = __uint_as_float((unsigned)(a & 0xffffffffull));
                float hi = __uint_as_float((unsigned)(a >> 32));
                float z  = lo + hi + Bs[c];
                outS[(size_t)r * HID + c] = 1.f / (1.f + __expf(-z));
            }
        }
    }
}

// ---------------------------------------------------------------------------
// Kernel 2: AI[rows[e]] += I[cols[e]]   (warp per 32 edges, red.v4)
// ---------------------------------------------------------------------------
__global__ void __launch_bounds__(256)
scatter_kernel(const int* __restrict__ rows, const int* __restrict__ cols) {
    const int warp = (blockIdx.x * 256 + threadIdx.x) >> 5;
    const int lane = threadIdx.x & 31;
    const int e0   = warp * 32;
    if (e0 >= N_EDGES) return;

    int r_l = rows[e0 + lane];
    int c_l = cols[e0 + lane];

    const float4* I4 = (const float4*)(g_SI + (size_t)N_NODES * HID);
#pragma unroll 1
    for (int i = 0; i < 32; i++) {
        int row = __shfl_sync(0xffffffffu, r_l, i);
        int col = __shfl_sync(0xffffffffu, c_l, i);
        float4 v = I4[(size_t)col * 32 + lane];
        float* p = g_AI + (size_t)row * HID + lane * 4;
        asm volatile("red.global.add.v4.f32 [%0], {%1, %2, %3, %4};"
                     :: "l"(p), "f"(v.x), "f"(v.y), "f"(v.z), "f"(v.w)
                     : "memory");
    }
}

// ---------------------------------------------------------------------------
// Kernel 3: epilogue  dS = -beta*AI*S ; dI = -dS - gamma*I ; dR = gamma*I ; 0
// ---------------------------------------------------------------------------
__global__ void __launch_bounds__(256)
epilogue_kernel(const float* __restrict__ x, float* __restrict__ out) {
    size_t idx = (size_t)blockIdx.x * 256 + threadIdx.x;  // < N*32
    size_t n   = idx >> 5;
    int    q   = (int)(idx & 31);

    float beta  = x[((size_t)3 * N_NODES + n) * HID + 0];
    float gamma = x[((size_t)3 * N_NODES + n) * HID + 1];

    size_t base = n * 32 + q;
    float4 S  = ((const float4*)g_SI)[base];
    float4 I  = ((const float4*)(g_SI + (size_t)N_NODES * HID))[base];
    float4 AI = ((const float4*)g_AI)[base];

    float4 dS, dI, dR;
    dS.x = -beta * AI.x * S.x;  dS.y = -beta * AI.y * S.y;
    dS.z = -beta * AI.z * S.z;  dS.w = -beta * AI.w * S.w;
    dI.x = -dS.x - gamma * I.x; dI.y = -dS.y - gamma * I.y;
    dI.z = -dS.z - gamma * I.z; dI.w = -dS.w - gamma * I.w;
    dR.x =  gamma * I.x;        dR.y =  gamma * I.y;
    dR.z =  gamma * I.z;        dR.w =  gamma * I.w;

    float4* o = (float4*)out;
    const size_t slab = (size_t)N_NODES * 32;
    o[base]            = dS;
    o[slab + base]     = dI;
    o[2 * slab + base] = dR;
    o[3 * slab + base] = make_float4(0.f, 0.f, 0.f, 0.f);
}

// ---------------------------------------------------------------------------
extern "C" void kernel_launch(void* const* d_in, const int* in_sizes, int n_in,
                              void* d_out, int out_size) {
    const float* x    = (const float*)d_in[0];
    const float* W    = (const float*)d_in[1];
    const float* b    = (const float*)d_in[2];
    const int*   rows = (const int*)d_in[3];   // jax int64 -> int32 (x64 off)
    const int*   cols = (const int*)d_in[4];
    float*       out  = (float*)d_out;

    const int smem = (128 * 128 + 128 * WPAD + 128) * 4;   // 132608 B
    cudaFuncSetAttribute(gemm_sigmoid_kernel,
                         cudaFuncAttributeMaxDynamicSharedMemorySize, smem);

    // 1) zero AI  (12.8M floats -> 3.2M float4)
    zero_ai_kernel<<<(N_NODES * HID / 4) / 256, 256>>>();

    // 2) S, I = sigmoid(x[s] @ W^T + b)
    dim3 ggrid((N_NODES + 127) / 128, 2);
    gemm_sigmoid_kernel<<<ggrid, 256, smem>>>(x, W, b);

    // 3) edge scatter-add
    int nwarps  = N_EDGES / 32;                 // 50000
    scatter_kernel<<<(nwarps * 32 + 255) / 256, 256>>>(rows, cols);

    // 4) epilogue
    epilogue_kernel<<<(N_NODES * 32 + 255) / 256, 256>>>(x, out);
}

// round 5
// speedup vs baseline: 1.1689x; 1.1689x over previous
#include <cuda_runtime.h>
#include <cuda_bf16.h>
#include <cstdint>

#define N_NODES 100000
#define HID     128
#define N_EDGES 1600000
#define NSCAN_BLOCKS 98   // 98*1024 = 100352 >= N_NODES
#define NE4 (N_EDGES / 4) // 400000 int4 elements

// Scratch (__device__ globals; no allocation allowed)
__device__ float g_SI[2u * N_NODES * HID];     // [0]=S, [1]=I  (102.4 MB)
__device__ int   g_cnt[N_NODES];               // histogram, then bucket cursor
__device__ int   g_start[N_NODES];             // exclusive prefix (row segment start)
__device__ int   g_blk[1024];                  // block sums for scan
__device__ int   g_scols[N_EDGES];             // cols sorted by destination row

// ---------------------------------------------------------------------------
// packed fp32x2 FMA (Blackwell FFMA2 — only reachable via PTX)
// ---------------------------------------------------------------------------
__device__ __forceinline__ void fma_f32x2(unsigned long long& d,
                                          unsigned long long a,
                                          unsigned long long b) {
    asm("fma.rn.f32x2 %0, %1, %2, %3;" : "=l"(d) : "l"(a), "l"(b), "l"(d));
}

// ---------------------------------------------------------------------------
// Kernel: S/I = sigmoid(x[s] @ W^T + b), s in {0,1}
// 128x128 block tile, 256 threads, 8x8 per-thread regs, f32x2 on k.
// ---------------------------------------------------------------------------
#define WPAD 130
__global__ void __launch_bounds__(256, 1)
gemm_sigmoid_kernel(const float* __restrict__ x,
                    const float* __restrict__ W,
                    const float* __restrict__ b) {
    extern __shared__ float sm[];
    float* Xs = sm;                     // 128*128
    float* Ws = sm + 128 * 128;         // 128*WPAD, layout [c][k]
    float* Bs = Ws + 128 * WPAD;        // 128

    const int s    = blockIdx.y;
    const int row0 = blockIdx.x * 128;
    const int tid  = threadIdx.x;

    for (int idx = tid; idx < 128 * 128; idx += 256) {
        int c = idx >> 7, k = idx & 127;
        Ws[c * WPAD + k] = W[idx];
    }
    if (tid < 128) Bs[tid] = b[tid];

    const float4* xs4 = (const float4*)(x + ((size_t)s * N_NODES + row0) * HID);
    for (int idx = tid; idx < 128 * 32; idx += 256)
        ((float4*)Xs)[idx] = xs4[idx];
    __syncthreads();

    const int ty = tid >> 4;       // 0..15 -> 8 rows each
    const int tx = tid & 15;       // 0..15 -> cols tx + 16*j

    unsigned long long acc[8][8];
#pragma unroll
    for (int i = 0; i < 8; i++)
#pragma unroll
        for (int j = 0; j < 8; j++) acc[i][j] = 0ull;

#pragma unroll 4
    for (int k = 0; k < 128; k += 2) {
        unsigned long long xv[8], wv[8];
#pragma unroll
        for (int i = 0; i < 8; i++)
            xv[i] = *(const unsigned long long*)(Xs + (ty * 8 + i) * 128 + k);
#pragma unroll
        for (int j = 0; j < 8; j++)
            wv[j] = *(const unsigned long long*)(Ws + (tx + 16 * j) * WPAD + k);
#pragma unroll
        for (int j = 0; j < 8; j++)
#pragma unroll
            for (int i = 0; i < 8; i++)
                fma_f32x2(acc[i][j], xv[i], wv[j]);
    }

    float* outS = g_SI + ((size_t)s * N_NODES + row0) * HID;
#pragma unroll
    for (int i = 0; i < 8; i++) {
        int r = ty * 8 + i;
        if (row0 + r < N_NODES) {
#pragma unroll
            for (int j = 0; j < 8; j++) {
                int c = tx + 16 * j;
                unsigned long long a = acc[i][j];
                float lo = __uint_as_float((unsigned)(a & 0xffffffffull));
                float hi = __uint_as_float((unsigned)(a >> 32));
                float z  = lo + hi + Bs[c];
                outS[(size_t)r * HID + c] = 1.f / (1.f + __expf(-z));
            }
        }
    }
}

// ---------------------------------------------------------------------------
// Counting sort of edges by destination row
// ---------------------------------------------------------------------------
__global__ void __launch_bounds__(1024) zero_cnt_kernel() {
    int i = blockIdx.x * 1024 + threadIdx.x;
    if (i < N_NODES) g_cnt[i] = 0;
}

__global__ void __launch_bounds__(256) hist_kernel(const int* __restrict__ rows) {
    int t = blockIdx.x * 256 + threadIdx.x;
    if (t >= NE4) return;                       // full coverage guard
    int4 r = ((const int4*)rows)[t];
    atomicAdd(&g_cnt[r.x], 1);
    atomicAdd(&g_cnt[r.y], 1);
    atomicAdd(&g_cnt[r.z], 1);
    atomicAdd(&g_cnt[r.w], 1);
}

__global__ void __launch_bounds__(1024) scan1_kernel() {
    __shared__ int sh[1024];
    int tid = threadIdx.x;
    int i   = blockIdx.x * 1024 + tid;
    int v   = (i < N_NODES) ? g_cnt[i] : 0;
    sh[tid] = v;
    __syncthreads();
#pragma unroll
    for (int off = 1; off < 1024; off <<= 1) {
        int t = (tid >= off) ? sh[tid - off] : 0;
        __syncthreads();
        sh[tid] += t;
        __syncthreads();
    }
    if (i < N_NODES) g_start[i] = sh[tid] - v;   // exclusive
    if (tid == 1023) g_blk[blockIdx.x] = sh[1023];
}

__global__ void __launch_bounds__(128) scan2_kernel() {
    __shared__ int sh[128];
    int tid = threadIdx.x;
    int v   = (tid < NSCAN_BLOCKS) ? g_blk[tid] : 0;
    sh[tid] = v;
    __syncthreads();
#pragma unroll
    for (int off = 1; off < 128; off <<= 1) {
        int t = (tid >= off) ? sh[tid - off] : 0;
        __syncthreads();
        sh[tid] += t;
        __syncthreads();
    }
    g_blk[tid] = sh[tid] - v;   // exclusive
}

__global__ void __launch_bounds__(1024) scan3_kernel() {
    int i = blockIdx.x * 1024 + threadIdx.x;
    if (i < N_NODES) {
        int s = g_start[i] + g_blk[i >> 10];
        g_start[i] = s;
        g_cnt[i]   = s;          // bucket cursor
    }
}

__global__ void __launch_bounds__(256)
bucket_kernel(const int* __restrict__ rows, const int* __restrict__ cols) {
    int t = blockIdx.x * 256 + threadIdx.x;
    if (t >= NE4) return;                       // full coverage guard
    int4 r = ((const int4*)rows)[t];
    int4 c = ((const int4*)cols)[t];
    int p0 = atomicAdd(&g_cnt[r.x], 1);
    int p1 = atomicAdd(&g_cnt[r.y], 1);
    int p2 = atomicAdd(&g_cnt[r.z], 1);
    int p3 = atomicAdd(&g_cnt[r.w], 1);
    g_scols[p0] = c.x;
    g_scols[p1] = c.y;
    g_scols[p2] = c.z;
    g_scols[p3] = c.w;
}

// ---------------------------------------------------------------------------
// Fused gather + epilogue: one warp per row.
//   AI = sum_{e in row} I[scols[e]]   (registers, no atomics)
//   dS = -beta*AI*S; dI = -dS - gamma*I; dR = gamma*I; slab3 = 0
// ---------------------------------------------------------------------------
__global__ void __launch_bounds__(256)
gather_epilogue_kernel(const float* __restrict__ x, float* __restrict__ out) {
    const int warp = (blockIdx.x * 256 + threadIdx.x) >> 5;
    const int lane = threadIdx.x & 31;
    if (warp >= N_NODES) return;
    const int row = warp;

    const int s0 = g_start[row];
    const int s1 = (row + 1 < N_NODES) ? g_start[row + 1] : N_EDGES;

    const float4* I4 = (const float4*)(g_SI + (size_t)N_NODES * HID);
    float4 a0 = make_float4(0.f, 0.f, 0.f, 0.f);
    float4 a1 = make_float4(0.f, 0.f, 0.f, 0.f);

    int i = s0;
    for (; i + 1 < s1; i += 2) {
        int c0 = g_scols[i];
        int c1 = g_scols[i + 1];
        float4 v0 = I4[(size_t)c0 * 32 + lane];
        float4 v1 = I4[(size_t)c1 * 32 + lane];
        a0.x += v0.x; a0.y += v0.y; a0.z += v0.z; a0.w += v0.w;
        a1.x += v1.x; a1.y += v1.y; a1.z += v1.z; a1.w += v1.w;
    }
    if (i < s1) {
        int c0 = g_scols[i];
        float4 v0 = I4[(size_t)c0 * 32 + lane];
        a0.x += v0.x; a0.y += v0.y; a0.z += v0.z; a0.w += v0.w;
    }
    float4 AI;
    AI.x = a0.x + a1.x; AI.y = a0.y + a1.y;
    AI.z = a0.z + a1.z; AI.w = a0.w + a1.w;

    const float beta  = x[((size_t)3 * N_NODES + row) * HID + 0];
    const float gamma = x[((size_t)3 * N_NODES + row) * HID + 1];

    const size_t base = (size_t)row * 32 + lane;
    float4 S = ((const float4*)g_SI)[base];
    float4 I = I4[base];

    float4 dS, dI, dR;
    dS.x = -beta * AI.x * S.x;  dS.y = -beta * AI.y * S.y;
    dS.z = -beta * AI.z * S.z;  dS.w = -beta * AI.w * S.w;
    dI.x = -dS.x - gamma * I.x; dI.y = -dS.y - gamma * I.y;
    dI.z = -dS.z - gamma * I.z; dI.w = -dS.w - gamma * I.w;
    dR.x =  gamma * I.x;        dR.y =  gamma * I.y;
    dR.z =  gamma * I.z;        dR.w =  gamma * I.w;

    float4* o = (float4*)out;
    const size_t slab = (size_t)N_NODES * 32;
    o[base]            = dS;
    o[slab + base]     = dI;
    o[2 * slab + base] = dR;
    o[3 * slab + base] = make_float4(0.f, 0.f, 0.f, 0.f);
}

// ---------------------------------------------------------------------------
extern "C" void kernel_launch(void* const* d_in, const int* in_sizes, int n_in,
                              void* d_out, int out_size) {
    const float* x    = (const float*)d_in[0];
    const float* W    = (const float*)d_in[1];
    const float* b    = (const float*)d_in[2];
    const int*   rows = (const int*)d_in[3];
    const int*   cols = (const int*)d_in[4];
    float*       out  = (float*)d_out;

    const int smem = (128 * 128 + 128 * WPAD + 128) * 4;   // 132608 B
    cudaFuncSetAttribute(gemm_sigmoid_kernel,
                         cudaFuncAttributeMaxDynamicSharedMemorySize, smem);

    // GEMM first (S/I needed by the final kernel only).
    dim3 ggrid((N_NODES + 127) / 128, 2);
    gemm_sigmoid_kernel<<<ggrid, 256, smem>>>(x, W, b);

    // Counting sort of edges by destination row (indices only).
    const int ebloks = (NE4 + 255) / 256;       // 1563 — full edge coverage
    zero_cnt_kernel<<<NSCAN_BLOCKS, 1024>>>();
    hist_kernel<<<ebloks, 256>>>(rows);
    scan1_kernel<<<NSCAN_BLOCKS, 1024>>>();
    scan2_kernel<<<1, 128>>>();
    scan3_kernel<<<NSCAN_BLOCKS, 1024>>>();
    bucket_kernel<<<ebloks, 256>>>(rows, cols);

    // Fused gather (register accumulation, no atomics) + epilogue.
    gather_epilogue_kernel<<<(N_NODES + 7) / 8, 256>>>(x, out);
}